// round 2
// baseline (speedup 1.0000x reference)
#include <cuda_runtime.h>
#include <math.h>

#define NHEADS 8
#define HC     32
#define HDIM   64
#define WDIM   64
#define HW     4096
#define CDIM   256
#define BDIM   8
#define LDIM   80

// ---------- scratch ----------
__device__ float g_wT[CDIM * 9 * CDIM];          // [(ci*9+tap)*256 + co], BN-folded
__device__ float g_beta2[CDIM];                  // beta - mean*inv
__device__ float g_attn[BDIM * NHEADS * HW];     // sigmoid gate per (b, head, pixel)

// packed f32x2 helpers (sm_103a)
#define FMA2(d, a, b) asm("fma.rn.f32x2 %0, %1, %2, %0;" : "+l"(d) : "l"(a), "l"(b))
#define PACK2(d, lo, hi) asm("mov.b64 %0, {%1, %2};" : "=l"(d) : "f"(lo), "f"(hi))
#define UNPACK2(lo, hi, s) asm("mov.b64 {%0, %1}, %2;" : "=f"(lo), "=f"(hi) : "l"(s))

// ---------- K0: fold BN into conv weights, transpose for coalesced loads ----------
__global__ void prep_kernel(const float* __restrict__ conv_w,
                            const float* __restrict__ gamma,
                            const float* __restrict__ beta,
                            const float* __restrict__ mean,
                            const float* __restrict__ var) {
    int idx = blockIdx.x * 256 + threadIdx.x;
    if (idx < CDIM * CDIM * 9) {
        int co  = idx / (CDIM * 9);
        int r   = idx % (CDIM * 9);
        int ci  = r / 9;
        int tap = r % 9;
        float inv = gamma[co] * rsqrtf(var[co] + 1e-3f);
        g_wT[(ci * 9 + tap) * CDIM + co] = conv_w[idx] * inv;
    }
    if (idx < CDIM) {
        float inv = gamma[idx] * rsqrtf(var[idx] + 1e-3f);
        g_beta2[idx] = beta[idx] - mean[idx] * inv;
    }
}

// ---------- K1: fused 1x1 proj + text attention + max + sigmoid*scale ----------
__global__ void __launch_bounds__(256) attn_kernel(
    const float* __restrict__ img,
    const float* __restrict__ text,
    const float* __restrict__ proj_w,
    const float* __restrict__ proj_b,
    const float* __restrict__ attn_bias,
    const float* __restrict__ scale) {

    __shared__ __align__(16) float W_s[HC * CDIM];   // [cc][cin]
    __shared__ __align__(16) float T_s[LDIM * HC];   // [n][cc]

    const int tid  = threadIdx.x;
    const int tile = blockIdx.x;
    const int head = blockIdx.y;
    const int b    = blockIdx.z;

    for (int i = tid; i < HC * CDIM; i += 256)
        W_s[i] = proj_w[head * HC * CDIM + i];
    for (int i = tid; i < LDIM * HC; i += 256) {
        int n = i >> 5, cc = i & 31;
        T_s[i] = text[(b * LDIM + n) * CDIM + head * HC + cc];
    }
    __syncthreads();

    const int pix = tile * 256 + tid;
    const float* imgp = img + ((size_t)b * CDIM) * HW + pix;

    float acc[HC];
    #pragma unroll
    for (int cc = 0; cc < HC; cc++) acc[cc] = proj_b[head * HC + cc];

    const float4* W4 = reinterpret_cast<const float4*>(W_s);
    #pragma unroll 2
    for (int cin = 0; cin < CDIM; cin += 4) {
        float v0 = imgp[(cin + 0) * HW];
        float v1 = imgp[(cin + 1) * HW];
        float v2 = imgp[(cin + 2) * HW];
        float v3 = imgp[(cin + 3) * HW];
        int q = cin >> 2;
        #pragma unroll
        for (int cc = 0; cc < HC; cc++) {
            float4 w = W4[cc * (CDIM / 4) + q];
            acc[cc] += w.x * v0 + w.y * v1 + w.z * v2 + w.w * v3;
        }
    }

    float best = -1e30f;
    #pragma unroll 2
    for (int n = 0; n < LDIM; n += 2) {
        float s0a = 0.f, s0b = 0.f, s1a = 0.f, s1b = 0.f;
        #pragma unroll
        for (int cc = 0; cc < HC; cc += 2) {
            s0a += acc[cc]     * T_s[n * HC + cc];
            s0b += acc[cc + 1] * T_s[n * HC + cc + 1];
            s1a += acc[cc]     * T_s[(n + 1) * HC + cc];
            s1b += acc[cc + 1] * T_s[(n + 1) * HC + cc + 1];
        }
        best = fmaxf(best, fmaxf(s0a + s0b, s1a + s1b));
    }

    const float inv_sqrt_hc = 0.17677669529663687f;
    float z = best * inv_sqrt_hc + attn_bias[head];
    float a = (1.0f / (1.0f + expf(-z))) * scale[head];
    g_attn[((b * NHEADS + head) << 12) + pix] = a;
}

// ---------- K2: 3x3 conv (BN folded) + gate, packed f32x2 math ----------
// block tile: 64(W) x 8(H) x 32 couts; thread: 4px(x) * 2px(y, packed) * 8co
#define CI_T 8
#define RS   80

__global__ void __launch_bounds__(256, 2) conv_gate_kernel(
    const float* __restrict__ img, float* __restrict__ out) {

    __shared__ __align__(16) float in_s[CI_T * 10 * RS];   // 25.6 KB
    __shared__ __align__(16) float w2_s[CI_T * 9 * 64];    // 18.4 KB duplicated pairs

    const int tid = threadIdx.x;
    const int tx  = tid & 15;
    const int ty  = (tid >> 4) & 3;
    const int cg  = tid >> 6;
    const int ht  = blockIdx.x;
    const int cob = blockIdx.y;
    const int b   = blockIdx.z;

    const int hbase = ht * 8;
    const float* imgb = img + (size_t)b * CDIM * HW;

    unsigned long long acc2[4][8];   // {row ty, row ty+4} packed
    #pragma unroll
    for (int j = 0; j < 4; j++)
        #pragma unroll
        for (int k = 0; k < 8; k++) acc2[j][k] = 0ULL;

    for (int cib = 0; cib < CDIM; cib += CI_T) {
        // input tile with halo
        for (int idx = tid; idx < CI_T * 10 * 66; idx += 256) {
            int ci = idx / 660;
            int r  = idx % 660;
            int sy = r / 66, sx = r % 66;
            int gy = hbase + sy - 1;
            int gx = sx - 1;
            float v = 0.f;
            if ((unsigned)gy < 64u && (unsigned)gx < 64u)
                v = imgb[(cib + ci) * HW + (gy << 6) + gx];
            in_s[ci * (10 * RS) + sy * RS + sx] = v;
        }
        // weights, duplicated into {w,w} pairs
        for (int idx = tid; idx < CI_T * 9 * 32; idx += 256) {
            int ci_tap = idx >> 5;
            int co     = idx & 31;
            float wv = g_wT[(cib * 9 + ci_tap) * CDIM + cob * 32 + co];
            w2_s[idx * 2]     = wv;
            w2_s[idx * 2 + 1] = wv;
        }
        __syncthreads();

        #pragma unroll 2
        for (int ci = 0; ci < CI_T; ci++) {
            const float* ins = &in_s[ci * (10 * RS)];
            #pragma unroll
            for (int t = 0; t < 9; t++) {
                const int ky = t / 3, kx = t % 3;
                const ulonglong2* wp =
                    reinterpret_cast<const ulonglong2*>(&w2_s[(ci * 9 + t) * 64 + cg * 16]);
                ulonglong2 wa = wp[0];   // broadcast within warp
                ulonglong2 wb = wp[1];
                ulonglong2 wc = wp[2];
                ulonglong2 wd = wp[3];
                #pragma unroll
                for (int j = 0; j < 4; j++) {
                    float v0 = ins[(ty + ky) * RS + tx + j * 16 + kx];
                    float v1 = ins[(ty + 4 + ky) * RS + tx + j * 16 + kx];
                    unsigned long long v2;
                    PACK2(v2, v0, v1);
                    FMA2(acc2[j][0], wa.x, v2);
                    FMA2(acc2[j][1], wa.y, v2);
                    FMA2(acc2[j][2], wb.x, v2);
                    FMA2(acc2[j][3], wb.y, v2);
                    FMA2(acc2[j][4], wc.x, v2);
                    FMA2(acc2[j][5], wc.y, v2);
                    FMA2(acc2[j][6], wd.x, v2);
                    FMA2(acc2[j][7], wd.y, v2);
                }
            }
        }
        __syncthreads();
    }

    // epilogue: +beta2, * attn gate, store
    float beta2v[8];
    #pragma unroll
    for (int k = 0; k < 8; k++) beta2v[k] = g_beta2[cob * 32 + cg * 8 + k];

    const float* attnp = &g_attn[((b * NHEADS + cob) << 12)];
    #pragma unroll
    for (int j = 0; j < 4; j++) {
        int gx  = tx + j * 16;
        int gy0 = hbase + ty;
        int gy1 = hbase + ty + 4;
        float a0 = attnp[(gy0 << 6) + gx];
        float a1 = attnp[(gy1 << 6) + gx];
        #pragma unroll
        for (int k = 0; k < 8; k++) {
            int co = cob * 32 + cg * 8 + k;
            float lo, hi;
            UNPACK2(lo, hi, acc2[j][k]);
            out[(((size_t)b * CDIM + co) << 12) + (gy0 << 6) + gx] = (lo + beta2v[k]) * a0;
            out[(((size_t)b * CDIM + co) << 12) + (gy1 << 6) + gx] = (hi + beta2v[k]) * a1;
        }
    }
}

// ---------- launch ----------
extern "C" void kernel_launch(void* const* d_in, const int* in_sizes, int n_in,
                              void* d_out, int out_size) {
    const float* img_feat   = (const float*)d_in[0];
    const float* text_feats = (const float*)d_in[1];
    const float* proj_w     = (const float*)d_in[2];
    const float* proj_b     = (const float*)d_in[3];
    const float* attn_bias  = (const float*)d_in[4];
    const float* scale      = (const float*)d_in[5];
    const float* conv_w     = (const float*)d_in[6];
    const float* bn_gamma   = (const float*)d_in[7];
    const float* bn_beta    = (const float*)d_in[8];
    const float* bn_mean    = (const float*)d_in[9];
    const float* bn_var     = (const float*)d_in[10];
    float* out = (float*)d_out;

    prep_kernel<<<(CDIM * CDIM * 9 + 255) / 256, 256>>>(conv_w, bn_gamma, bn_beta, bn_mean, bn_var);

    dim3 g1(HW / 256, NHEADS, BDIM);
    attn_kernel<<<g1, 256>>>(img_feat, text_feats, proj_w, proj_b, attn_bias, scale);

    dim3 g2(HDIM / 8, CDIM / 32, BDIM);
    conv_gate_kernel<<<g2, 256>>>(img_feat, out);
}

// round 4
// speedup vs baseline: 2.5015x; 2.5015x over previous
#include <cuda_runtime.h>
#include <cstdint>
#include <math.h>

#define NHEADS 8
#define HC     32
#define HW     4096
#define CDIM   256
#define BDIM   8
#define LDIM   80

// ================= scratch =================
__device__ float g_wB[9 * CDIM * CDIM];          // [tap][ci][co], BN-folded, tf32-rounded
__device__ float g_beta2[CDIM];
__device__ float g_attn[BDIM * NHEADS * HW];

__device__ __forceinline__ float to_tf32(float x) {
    uint32_t u;
    asm("cvt.rna.tf32.f32 %0, %1;" : "=r"(u) : "f"(x));
    return __uint_as_float(u);
}

// m16n8k8 tf32 mma (legacy mma.sync — valid on sm_103 plain target)
__device__ __forceinline__ void mma_tf32(float* c,
                                         uint32_t a0, uint32_t a1, uint32_t a2, uint32_t a3,
                                         uint32_t b0, uint32_t b1) {
    asm volatile(
        "mma.sync.aligned.m16n8k8.row.col.f32.tf32.tf32.f32 "
        "{%0,%1,%2,%3}, {%4,%5,%6,%7}, {%8,%9}, {%0,%1,%2,%3};"
        : "+f"(c[0]), "+f"(c[1]), "+f"(c[2]), "+f"(c[3])
        : "r"(a0), "r"(a1), "r"(a2), "r"(a3), "r"(b0), "r"(b1));
}

// ================= K0: weight prep =================
__global__ void prep_kernel(const float* __restrict__ conv_w,
                            const float* __restrict__ gamma,
                            const float* __restrict__ beta,
                            const float* __restrict__ mean,
                            const float* __restrict__ var) {
    int idx = blockIdx.x * 256 + threadIdx.x;
    if (idx < CDIM * CDIM * 9) {
        int co  = idx / (CDIM * 9);
        int r   = idx % (CDIM * 9);
        int ci  = r / 9;
        int tap = r % 9;
        float inv = gamma[co] * rsqrtf(var[co] + 1e-3f);
        g_wB[(tap * CDIM + ci) * CDIM + co] = to_tf32(conv_w[idx] * inv);
    }
    if (idx < CDIM) {
        float inv = gamma[idx] * rsqrtf(var[idx] + 1e-3f);
        g_beta2[idx] = beta[idx] - mean[idx] * inv;
    }
}

// ================= K1: attn gate (fp32, unchanged) =================
__global__ void __launch_bounds__(256) attn_kernel(
    const float* __restrict__ img,
    const float* __restrict__ text,
    const float* __restrict__ proj_w,
    const float* __restrict__ proj_b,
    const float* __restrict__ attn_bias,
    const float* __restrict__ scale) {

    __shared__ __align__(16) float W_s[HC * CDIM];
    __shared__ __align__(16) float T_s[LDIM * HC];

    const int tid  = threadIdx.x;
    const int tile = blockIdx.x;
    const int head = blockIdx.y;
    const int b    = blockIdx.z;

    for (int i = tid; i < HC * CDIM; i += 256)
        W_s[i] = proj_w[head * HC * CDIM + i];
    for (int i = tid; i < LDIM * HC; i += 256) {
        int n = i >> 5, cc = i & 31;
        T_s[i] = text[(b * LDIM + n) * CDIM + head * HC + cc];
    }
    __syncthreads();

    const int pix = tile * 256 + tid;
    const float* imgp = img + ((size_t)b * CDIM) * HW + pix;

    float acc[HC];
    #pragma unroll
    for (int cc = 0; cc < HC; cc++) acc[cc] = proj_b[head * HC + cc];

    const float4* W4 = reinterpret_cast<const float4*>(W_s);
    #pragma unroll 2
    for (int cin = 0; cin < CDIM; cin += 4) {
        float v0 = imgp[(cin + 0) * HW];
        float v1 = imgp[(cin + 1) * HW];
        float v2 = imgp[(cin + 2) * HW];
        float v3 = imgp[(cin + 3) * HW];
        int q = cin >> 2;
        #pragma unroll
        for (int cc = 0; cc < HC; cc++) {
            float4 w = W4[cc * (CDIM / 4) + q];
            acc[cc] += w.x * v0 + w.y * v1 + w.z * v2 + w.w * v3;
        }
    }

    float best = -1e30f;
    #pragma unroll 2
    for (int n = 0; n < LDIM; n += 2) {
        float s0a = 0.f, s0b = 0.f, s1a = 0.f, s1b = 0.f;
        #pragma unroll
        for (int cc = 0; cc < HC; cc += 2) {
            s0a += acc[cc]     * T_s[n * HC + cc];
            s0b += acc[cc + 1] * T_s[n * HC + cc + 1];
            s1a += acc[cc]     * T_s[(n + 1) * HC + cc];
            s1b += acc[cc + 1] * T_s[(n + 1) * HC + cc + 1];
        }
        best = fmaxf(best, fmaxf(s0a + s0b, s1a + s1b));
    }

    float z = best * 0.17677669529663687f + attn_bias[head];
    float a = (1.0f / (1.0f + expf(-z))) * scale[head];
    g_attn[((b * NHEADS + head) << 12) + pix] = a;
}

// ================= K2: mma.sync tf32 implicit-GEMM conv + BN + gate =================
// CTA tile: M=128 pixels (2 image rows) x N=128 couts. 8 warps: 4(M) x 2(N).
// Warp tile 32x64. K loop: 32 rounds of 8 cin, 9 taps each (k8 per tap).
// A fragments loaded directly from raw halo tile (tap offsets in the address).

#define RAW_RS  70         // raw row stride (floats): bank-safe (ci-stride 280 ≡ 24 mod 32)
#define RAW_CS  280        // per-ci stride = 4 rows * 70
#define W_RS    136        // weight row stride: bank-safe (136 ≡ 8 mod 32)

__global__ void __launch_bounds__(256, 2) conv_mma_kernel(
    const float* __restrict__ img, float* __restrict__ out) {

    __shared__ __align__(16) float raw[8 * RAW_CS];      //  8960 B
    __shared__ __align__(16) float wsm[72 * W_RS];       // 39168 B
    __shared__ float b2s[128];

    const int tid  = threadIdx.x;
    const int wid  = tid >> 5;
    const int lane = tid & 31;
    const int g    = lane >> 2;     // group id
    const int t    = lane & 3;      // thread-in-group

    const int bM = blockIdx.x;           // 0..255
    const int bN = blockIdx.y;           // 0..1
    const int b  = bM >> 5;
    const int y0 = (bM & 31) << 1;       // 2 image rows per CTA
    const int wm = (wid & 3) * 32;
    const int wn = (wid >> 2) * 64;

    const float* imgb = img + (size_t)b * CDIM * HW;

    if (tid < 128) b2s[tid] = g_beta2[bN * 128 + tid];

    float c[2][8][4];
    #pragma unroll
    for (int mt = 0; mt < 2; mt++)
        #pragma unroll
        for (int nt = 0; nt < 8; nt++)
            #pragma unroll
            for (int i = 0; i < 4; i++) c[mt][nt][i] = 0.f;

    for (int cib = 0; cib < 32; cib++) {
        __syncthreads();
        // ---- stage raw halo: 8 ci x 4 rows x 66 cols (tf32-rounded) ----
        for (int i = tid; i < 8 * 4 * 66; i += 256) {
            int ci = i / 264;
            int r  = i % 264;
            int ry = r / 66, rx = r % 66;
            int gy = y0 - 1 + ry;
            int gx = rx - 1;
            float v = 0.f;
            if ((unsigned)gy < 64u && (unsigned)gx < 64u)
                v = imgb[(cib * 8 + ci) * HW + (gy << 6) + gx];
            raw[ci * RAW_CS + ry * RAW_RS + rx] = to_tf32(v);
        }
        // ---- stage weights: 72 k-rows (tap*8+ci) x 128 couts ----
        for (int i = tid; i < 72 * 32; i += 256) {
            int row = i >> 5;            // tap*8 + ci
            int q   = i & 31;            // float4 index
            int tap = row >> 3, ci = row & 7;
            float4 v = *reinterpret_cast<const float4*>(
                g_wB + ((size_t)(tap * CDIM + cib * 8 + ci)) * CDIM + bN * 128 + q * 4);
            *reinterpret_cast<float4*>(&wsm[row * W_RS + q * 4]) = v;
        }
        __syncthreads();

        for (int ky = 0; ky < 3; ky++) {
            #pragma unroll
            for (int kx = 0; kx < 3; kx++) {
                const int tap = ky * 3 + kx;
                // A fragments per mt (direct from halo; k = t and t+4 -> ci)
                uint32_t a[2][4];
                #pragma unroll
                for (int mt = 0; mt < 2; mt++) {
                    int m    = wm + mt * 16 + g;
                    int prow = m >> 6, pcol = m & 63;
                    const float* p = &raw[t * RAW_CS + (prow + ky) * RAW_RS + (pcol + kx)];
                    a[mt][0] = __float_as_uint(p[0]);
                    a[mt][1] = __float_as_uint(p[8]);                 // row +8 (same prow)
                    a[mt][2] = __float_as_uint(p[4 * RAW_CS]);        // k +4
                    a[mt][3] = __float_as_uint(p[4 * RAW_CS + 8]);
                }
                // B fragments per nt + mma
                const float* wrow = &wsm[(tap * 8 + t) * W_RS + wn + g];
                #pragma unroll
                for (int nt = 0; nt < 8; nt++) {
                    uint32_t b0 = __float_as_uint(wrow[nt * 8]);
                    uint32_t b1 = __float_as_uint(wrow[nt * 8 + 4 * W_RS]);
                    mma_tf32(c[0][nt], a[0][0], a[0][1], a[0][2], a[0][3], b0, b1);
                    mma_tf32(c[1][nt], a[1][0], a[1][1], a[1][2], a[1][3], b0, b1);
                }
            }
        }
    }

    // ---- epilogue: +beta2, * gate, store ----
    #pragma unroll
    for (int mt = 0; mt < 2; mt++) {
        #pragma unroll
        for (int rr = 0; rr < 2; rr++) {
            int m   = wm + mt * 16 + g + rr * 8;
            int pix = (y0 << 6) + m;
            #pragma unroll
            for (int nt = 0; nt < 8; nt++) {
                int co = bN * 128 + wn + nt * 8 + 2 * t;
                float gate = g_attn[((b * NHEADS + (co >> 5)) << 12) + pix];
                float v0 = c[mt][nt][rr * 2 + 0] + b2s[wn + nt * 8 + 2 * t];
                float v1 = c[mt][nt][rr * 2 + 1] + b2s[wn + nt * 8 + 2 * t + 1];
                out[(((size_t)b * CDIM + co) << 12) + pix]       = v0 * gate;
                out[(((size_t)b * CDIM + co + 1) << 12) + pix]   = v1 * gate;
            }
        }
    }
}

// ================= launch =================
extern "C" void kernel_launch(void* const* d_in, const int* in_sizes, int n_in,
                              void* d_out, int out_size) {
    const float* img_feat   = (const float*)d_in[0];
    const float* text_feats = (const float*)d_in[1];
    const float* proj_w     = (const float*)d_in[2];
    const float* proj_b     = (const float*)d_in[3];
    const float* attn_bias  = (const float*)d_in[4];
    const float* scale      = (const float*)d_in[5];
    const float* conv_w     = (const float*)d_in[6];
    const float* bn_gamma   = (const float*)d_in[7];
    const float* bn_beta    = (const float*)d_in[8];
    const float* bn_mean    = (const float*)d_in[9];
    const float* bn_var     = (const float*)d_in[10];
    float* out = (float*)d_out;

    prep_kernel<<<(CDIM * CDIM * 9 + 255) / 256, 256>>>(conv_w, bn_gamma, bn_beta, bn_mean, bn_var);

    dim3 g1(HW / 256, NHEADS, BDIM);
    attn_kernel<<<g1, 256>>>(img_feat, text_feats, proj_w, proj_b, attn_bias, scale);

    dim3 g2(256, 2);
    conv_mma_kernel<<<g2, 256>>>(img_feat, out);
}

// round 5
// speedup vs baseline: 2.7014x; 1.0799x over previous
#include <cuda_runtime.h>
#include <cstdint>
#include <math.h>

#define NHEADS 8
#define HC     32
#define HW     4096
#define CDIM   256
#define BDIM   8
#define LDIM   80

// ================= scratch =================
__device__ float g_wB[9 * CDIM * CDIM];          // [tap][ci][co], BN-folded, tf32-rounded
__device__ float g_beta2[CDIM];
__device__ float g_attn[BDIM * NHEADS * HW];     // gate
__device__ float g_U[BDIM * NHEADS * CDIM * LDIM]; // fused proj*text, tf32-rounded, incl 1/sqrt(hc)
__device__ float g_c[BDIM * NHEADS * LDIM];        // per-token additive const incl bias

__device__ __forceinline__ float to_tf32(float x) {
    uint32_t u;
    asm("cvt.rna.tf32.f32 %0, %1;" : "=r"(u) : "f"(x));
    return __uint_as_float(u);
}

// m16n8k8 tf32 mma (legacy mma.sync — valid on plain sm_103 target)
__device__ __forceinline__ void mma_tf32(float* c,
                                         uint32_t a0, uint32_t a1, uint32_t a2, uint32_t a3,
                                         uint32_t b0, uint32_t b1) {
    asm volatile(
        "mma.sync.aligned.m16n8k8.row.col.f32.tf32.tf32.f32 "
        "{%0,%1,%2,%3}, {%4,%5,%6,%7}, {%8,%9}, {%0,%1,%2,%3};"
        : "+f"(c[0]), "+f"(c[1]), "+f"(c[2]), "+f"(c[3])
        : "r"(a0), "r"(a1), "r"(a2), "r"(a3), "r"(b0), "r"(b1));
}

// ================= K0: conv weight prep =================
__global__ void prep_kernel(const float* __restrict__ conv_w,
                            const float* __restrict__ gamma,
                            const float* __restrict__ beta,
                            const float* __restrict__ mean,
                            const float* __restrict__ var) {
    int idx = blockIdx.x * 256 + threadIdx.x;
    if (idx < CDIM * CDIM * 9) {
        int co  = idx / (CDIM * 9);
        int r   = idx % (CDIM * 9);
        int ci  = r / 9;
        int tap = r % 9;
        float inv = gamma[co] * rsqrtf(var[co] + 1e-3f);
        g_wB[(tap * CDIM + ci) * CDIM + co] = to_tf32(conv_w[idx] * inv);
    }
    if (idx < CDIM) {
        float inv = gamma[idx] * rsqrtf(var[idx] + 1e-3f);
        g_beta2[idx] = beta[idx] - mean[idx] * inv;
    }
}

// ================= K0b: attn prep — U = W_h^T T_h^T, c = b_h . T_h[n] =================
// grid (BDIM, NHEADS), 256 threads
__global__ void __launch_bounds__(256) prep_attn_kernel(
    const float* __restrict__ text,
    const float* __restrict__ proj_w,
    const float* __restrict__ proj_b,
    const float* __restrict__ attn_bias) {

    __shared__ float W_s[HC * CDIM];        // [cc][ci]
    __shared__ float T_s[LDIM * 33];        // [n][cc], padded

    const int tid = threadIdx.x;
    const int b   = blockIdx.x;
    const int h   = blockIdx.y;
    const float invs = 0.17677669529663687f;   // 1/sqrt(32)

    for (int i = tid; i < HC * CDIM; i += 256)
        W_s[i] = proj_w[(h * HC) * CDIM + i];
    for (int i = tid; i < LDIM * HC; i += 256) {
        int n = i >> 5, cc = i & 31;
        T_s[n * 33 + cc] = text[(b * LDIM + n) * CDIM + h * HC + cc];
    }
    __syncthreads();

    for (int i = tid; i < CDIM * LDIM; i += 256) {
        int ci = i / LDIM, n = i % LDIM;
        float u = 0.f;
        #pragma unroll
        for (int cc = 0; cc < HC; cc++)
            u += W_s[cc * CDIM + ci] * T_s[n * 33 + cc];
        g_U[((b * NHEADS + h) * CDIM + ci) * LDIM + n] = to_tf32(u * invs);
    }
    if (tid < LDIM) {
        float cb = 0.f;
        #pragma unroll
        for (int cc = 0; cc < HC; cc++)
            cb += proj_b[h * HC + cc] * T_s[tid * 33 + cc];
        g_c[(b * NHEADS + h) * LDIM + tid] = cb * invs + attn_bias[h];
    }
}

// ================= K1: attn gate via tf32 mma + max/sigmoid epilogue =================
// CTA: M=128 pixels x N=80 tokens, K=256. 8 warps 4Mx2N, warp tile 32x40.
#define A_RS 136    // banks g + 8t : conflict-free
#define U_RS 88     // banks 24t + g : conflict-free

__global__ void __launch_bounds__(256, 2) attn_mma_kernel(
    const float* __restrict__ img, const float* __restrict__ scale) {

    __shared__ __align__(16) float as_[32 * A_RS];   // 17.4 KB
    __shared__ __align__(16) float us_[32 * U_RS];   // 11.3 KB
    __shared__ float csm[LDIM];
    __shared__ float maxbuf[2 * 128];

    const int tid  = threadIdx.x;
    const int wid  = tid >> 5;
    const int lane = tid & 31;
    const int g    = lane >> 2;
    const int t    = lane & 3;

    const int b    = blockIdx.x >> 5;
    const int p0   = (blockIdx.x & 31) << 7;   // 128 pixels
    const int h    = blockIdx.y;
    const int wm   = (wid & 3) * 32;
    const int wn_i = wid >> 2;
    const int wn   = wn_i * 40;

    if (tid < LDIM) csm[tid] = g_c[(b * NHEADS + h) * LDIM + tid];

    float c[2][5][4];
    #pragma unroll
    for (int mt = 0; mt < 2; mt++)
        #pragma unroll
        for (int nt = 0; nt < 5; nt++)
            #pragma unroll
            for (int i = 0; i < 4; i++) c[mt][nt][i] = 0.f;

    const float* imgb = img + (size_t)b * CDIM * HW + p0;
    const float* Ub   = g_U + ((size_t)(b * NHEADS + h) * CDIM) * LDIM;

    for (int kb = 0; kb < 8; kb++) {
        __syncthreads();
        // stage A: 32 ci x 128 pixels
        for (int i = tid; i < 32 * 128; i += 256) {
            int ci = i >> 7, px = i & 127;
            as_[ci * A_RS + px] = to_tf32(imgb[(kb * 32 + ci) * HW + px]);
        }
        // stage U: 32 k x 80 n
        for (int i = tid; i < 32 * LDIM; i += 256) {
            int k = i / LDIM, n = i % LDIM;
            us_[k * U_RS + n] = Ub[(kb * 32 + k) * LDIM + n];
        }
        __syncthreads();

        #pragma unroll
        for (int kc = 0; kc < 4; kc++) {
            uint32_t a[2][4];
            #pragma unroll
            for (int mt = 0; mt < 2; mt++) {
                const float* p = &as_[(kc * 8 + t) * A_RS + wm + mt * 16 + g];
                a[mt][0] = __float_as_uint(p[0]);
                a[mt][1] = __float_as_uint(p[8]);
                a[mt][2] = __float_as_uint(p[4 * A_RS]);
                a[mt][3] = __float_as_uint(p[4 * A_RS + 8]);
            }
            const float* ur = &us_[(kc * 8 + t) * U_RS + wn + g];
            #pragma unroll
            for (int nt = 0; nt < 5; nt++) {
                uint32_t b0 = __float_as_uint(ur[nt * 8]);
                uint32_t b1 = __float_as_uint(ur[nt * 8 + 4 * U_RS]);
                mma_tf32(c[0][nt], a[0][0], a[0][1], a[0][2], a[0][3], b0, b1);
                mma_tf32(c[1][nt], a[1][0], a[1][1], a[1][2], a[1][3], b0, b1);
            }
        }
    }

    // epilogue: +c[n], max over tokens, cross-warp combine, sigmoid*scale
    #pragma unroll
    for (int mt = 0; mt < 2; mt++) {
        #pragma unroll
        for (int rr = 0; rr < 2; rr++) {
            float mx = -1e30f;
            #pragma unroll
            for (int nt = 0; nt < 5; nt++) {
                int n0 = wn + nt * 8 + 2 * t;
                mx = fmaxf(mx, fmaxf(c[mt][nt][rr * 2] + csm[n0],
                                     c[mt][nt][rr * 2 + 1] + csm[n0 + 1]));
            }
            mx = fmaxf(mx, __shfl_xor_sync(0xFFFFFFFF, mx, 1));
            mx = fmaxf(mx, __shfl_xor_sync(0xFFFFFFFF, mx, 2));
            if (t == 0)
                maxbuf[wn_i * 128 + wm + mt * 16 + rr * 8 + g] = mx;
        }
    }
    __syncthreads();
    if (tid < 128) {
        float z = fmaxf(maxbuf[tid], maxbuf[128 + tid]);
        float a = (1.0f / (1.0f + expf(-z))) * scale[h];
        g_attn[((b * NHEADS + h) << 12) + p0 + tid] = a;
    }
}

// ================= K2: mma.sync tf32 implicit-GEMM conv + BN + gate (round-4) =================
#define RAW_RS  70
#define RAW_CS  280
#define W_RS    136

__global__ void __launch_bounds__(256, 2) conv_mma_kernel(
    const float* __restrict__ img, float* __restrict__ out) {

    __shared__ __align__(16) float raw[8 * RAW_CS];
    __shared__ __align__(16) float wsm[72 * W_RS];
    __shared__ float b2s[128];

    const int tid  = threadIdx.x;
    const int wid  = tid >> 5;
    const int lane = tid & 31;
    const int g    = lane >> 2;
    const int t    = lane & 3;

    const int bM = blockIdx.x;
    const int bN = blockIdx.y;
    const int b  = bM >> 5;
    const int y0 = (bM & 31) << 1;
    const int wm = (wid & 3) * 32;
    const int wn = (wid >> 2) * 64;

    const float* imgb = img + (size_t)b * CDIM * HW;

    if (tid < 128) b2s[tid] = g_beta2[bN * 128 + tid];

    float c[2][8][4];
    #pragma unroll
    for (int mt = 0; mt < 2; mt++)
        #pragma unroll
        for (int nt = 0; nt < 8; nt++)
            #pragma unroll
            for (int i = 0; i < 4; i++) c[mt][nt][i] = 0.f;

    for (int cib = 0; cib < 32; cib++) {
        __syncthreads();
        for (int i = tid; i < 8 * 4 * 66; i += 256) {
            int ci = i / 264;
            int r  = i % 264;
            int ry = r / 66, rx = r % 66;
            int gy = y0 - 1 + ry;
            int gx = rx - 1;
            float v = 0.f;
            if ((unsigned)gy < 64u && (unsigned)gx < 64u)
                v = imgb[(cib * 8 + ci) * HW + (gy << 6) + gx];
            raw[ci * RAW_CS + ry * RAW_RS + rx] = to_tf32(v);
        }
        for (int i = tid; i < 72 * 32; i += 256) {
            int row = i >> 5;
            int q   = i & 31;
            int tap = row >> 3, ci = row & 7;
            float4 v = *reinterpret_cast<const float4*>(
                g_wB + ((size_t)(tap * CDIM + cib * 8 + ci)) * CDIM + bN * 128 + q * 4);
            *reinterpret_cast<float4*>(&wsm[row * W_RS + q * 4]) = v;
        }
        __syncthreads();

        for (int ky = 0; ky < 3; ky++) {
            #pragma unroll
            for (int kx = 0; kx < 3; kx++) {
                const int tap = ky * 3 + kx;
                uint32_t a[2][4];
                #pragma unroll
                for (int mt = 0; mt < 2; mt++) {
                    int m    = wm + mt * 16 + g;
                    int prow = m >> 6, pcol = m & 63;
                    const float* p = &raw[t * RAW_CS + (prow + ky) * RAW_RS + (pcol + kx)];
                    a[mt][0] = __float_as_uint(p[0]);
                    a[mt][1] = __float_as_uint(p[8]);
                    a[mt][2] = __float_as_uint(p[4 * RAW_CS]);
                    a[mt][3] = __float_as_uint(p[4 * RAW_CS + 8]);
                }
                const float* wrow = &wsm[(tap * 8 + t) * W_RS + wn + g];
                #pragma unroll
                for (int nt = 0; nt < 8; nt++) {
                    uint32_t b0 = __float_as_uint(wrow[nt * 8]);
                    uint32_t b1 = __float_as_uint(wrow[nt * 8 + 4 * W_RS]);
                    mma_tf32(c[0][nt], a[0][0], a[0][1], a[0][2], a[0][3], b0, b1);
                    mma_tf32(c[1][nt], a[1][0], a[1][1], a[1][2], a[1][3], b0, b1);
                }
            }
        }
    }

    #pragma unroll
    for (int mt = 0; mt < 2; mt++) {
        #pragma unroll
        for (int rr = 0; rr < 2; rr++) {
            int m   = wm + mt * 16 + g + rr * 8;
            int pix = (y0 << 6) + m;
            #pragma unroll
            for (int nt = 0; nt < 8; nt++) {
                int co = bN * 128 + wn + nt * 8 + 2 * t;
                float gate = g_attn[((b * NHEADS + (co >> 5)) << 12) + pix];
                float v0 = c[mt][nt][rr * 2 + 0] + b2s[wn + nt * 8 + 2 * t];
                float v1 = c[mt][nt][rr * 2 + 1] + b2s[wn + nt * 8 + 2 * t + 1];
                out[(((size_t)b * CDIM + co) << 12) + pix]     = v0 * gate;
                out[(((size_t)b * CDIM + co + 1) << 12) + pix] = v1 * gate;
            }
        }
    }
}

// ================= launch =================
extern "C" void kernel_launch(void* const* d_in, const int* in_sizes, int n_in,
                              void* d_out, int out_size) {
    const float* img_feat   = (const float*)d_in[0];
    const float* text_feats = (const float*)d_in[1];
    const float* proj_w     = (const float*)d_in[2];
    const float* proj_b     = (const float*)d_in[3];
    const float* attn_bias  = (const float*)d_in[4];
    const float* scale      = (const float*)d_in[5];
    const float* conv_w     = (const float*)d_in[6];
    const float* bn_gamma   = (const float*)d_in[7];
    const float* bn_beta    = (const float*)d_in[8];
    const float* bn_mean    = (const float*)d_in[9];
    const float* bn_var     = (const float*)d_in[10];
    float* out = (float*)d_out;

    prep_kernel<<<(CDIM * CDIM * 9 + 255) / 256, 256>>>(conv_w, bn_gamma, bn_beta, bn_mean, bn_var);

    dim3 gp(BDIM, NHEADS);
    prep_attn_kernel<<<gp, 256>>>(text_feats, proj_w, proj_b, attn_bias);

    dim3 g1(BDIM * 32, NHEADS);
    attn_mma_kernel<<<g1, 256>>>(img_feat, scale);

    dim3 g2(256, 2);
    conv_mma_kernel<<<g2, 256>>>(img_feat, out);
}

// round 6
// speedup vs baseline: 2.9583x; 1.0951x over previous
#include <cuda_runtime.h>
#include <cstdint>
#include <math.h>

#define NHEADS 8
#define HC     32
#define HW     4096
#define CDIM   256
#define BDIM   8
#define LDIM   80

// ================= scratch =================
__device__ float g_wB[9 * CDIM * CDIM];            // [tap][ci][co], BN-folded, tf32-rounded
__device__ float g_beta2[CDIM];
__device__ float g_attn[BDIM * NHEADS * HW];
__device__ float g_U[BDIM * NHEADS * CDIM * LDIM]; // [bh][ci][n], tf32-rounded, incl 1/sqrt(hc)
__device__ float g_c[BDIM * NHEADS * LDIM];

__device__ __forceinline__ float to_tf32(float x) {
    uint32_t u;
    asm("cvt.rna.tf32.f32 %0, %1;" : "=r"(u) : "f"(x));
    return __uint_as_float(u);
}
__device__ __forceinline__ uint32_t smem_u32(const void* p) {
    uint32_t a;
    asm("{ .reg .u64 t; cvta.to.shared.u64 t, %1; cvt.u32.u64 %0, t; }" : "=r"(a) : "l"(p));
    return a;
}
__device__ __forceinline__ void cp_async16(uint32_t dst, const void* src) {
    asm volatile("cp.async.ca.shared.global [%0], [%1], 16;" :: "r"(dst), "l"(src));
}
#define CP_COMMIT() asm volatile("cp.async.commit_group;" ::: "memory")
#define CP_WAIT1()  asm volatile("cp.async.wait_group 1;" ::: "memory")
#define CP_WAIT0()  asm volatile("cp.async.wait_group 0;" ::: "memory")

__device__ __forceinline__ void mma_tf32(float* c,
                                         uint32_t a0, uint32_t a1, uint32_t a2, uint32_t a3,
                                         uint32_t b0, uint32_t b1) {
    asm volatile(
        "mma.sync.aligned.m16n8k8.row.col.f32.tf32.tf32.f32 "
        "{%0,%1,%2,%3}, {%4,%5,%6,%7}, {%8,%9}, {%0,%1,%2,%3};"
        : "+f"(c[0]), "+f"(c[1]), "+f"(c[2]), "+f"(c[3])
        : "r"(a0), "r"(a1), "r"(a2), "r"(a3), "r"(b0), "r"(b1));
}

// ================= K0: conv weight prep =================
__global__ void prep_kernel(const float* __restrict__ conv_w,
                            const float* __restrict__ gamma,
                            const float* __restrict__ beta,
                            const float* __restrict__ mean,
                            const float* __restrict__ var) {
    int idx = blockIdx.x * 256 + threadIdx.x;
    if (idx < CDIM * CDIM * 9) {
        int co  = idx / (CDIM * 9);
        int r   = idx % (CDIM * 9);
        int ci  = r / 9;
        int tap = r % 9;
        float inv = gamma[co] * rsqrtf(var[co] + 1e-3f);
        g_wB[(tap * CDIM + ci) * CDIM + co] = to_tf32(conv_w[idx] * inv);
    }
    if (idx < CDIM) {
        float inv = gamma[idx] * rsqrtf(var[idx] + 1e-3f);
        g_beta2[idx] = beta[idx] - mean[idx] * inv;
    }
}

// ================= K0b: attn prep =================
__global__ void __launch_bounds__(256) prep_attn_kernel(
    const float* __restrict__ text,
    const float* __restrict__ proj_w,
    const float* __restrict__ proj_b,
    const float* __restrict__ attn_bias) {

    __shared__ float W_s[HC * CDIM];
    __shared__ float T_s[LDIM * 33];

    const int tid = threadIdx.x;
    const int b   = blockIdx.x;
    const int h   = blockIdx.y;
    const float invs = 0.17677669529663687f;

    for (int i = tid; i < HC * CDIM; i += 256)
        W_s[i] = proj_w[(h * HC) * CDIM + i];
    for (int i = tid; i < LDIM * HC; i += 256) {
        int n = i >> 5, cc = i & 31;
        T_s[n * 33 + cc] = text[(b * LDIM + n) * CDIM + h * HC + cc];
    }
    __syncthreads();

    for (int i = tid; i < CDIM * LDIM; i += 256) {
        int ci = i / LDIM, n = i % LDIM;
        float u = 0.f;
        #pragma unroll
        for (int cc = 0; cc < HC; cc++)
            u += W_s[cc * CDIM + ci] * T_s[n * 33 + cc];
        g_U[((b * NHEADS + h) * CDIM + ci) * LDIM + n] = to_tf32(u * invs);
    }
    if (tid < LDIM) {
        float cb = 0.f;
        #pragma unroll
        for (int cc = 0; cc < HC; cc++)
            cb += proj_b[h * HC + cc] * T_s[tid * 33 + cc];
        g_c[(b * NHEADS + h) * LDIM + tid] = cb * invs + attn_bias[h];
    }
}

// ================= K1: attn gate — A staged once, heads looped inside =================
#define A_RS 136
#define U_RS 88
// smem layout (floats): AS[256*136] | US0[32*88] | US1[32*88] | CSM[80] | MAX[256]
#define AT_US0  (256 * A_RS)
#define AT_US1  (AT_US0 + 32 * U_RS)
#define AT_CSM  (AT_US1 + 32 * U_RS)
#define AT_MAX  (AT_CSM + 80)
#define AT_TOT  (AT_MAX + 256)

__global__ void __launch_bounds__(256) attn_mma_kernel(
    const float* __restrict__ img, const float* __restrict__ scale) {

    extern __shared__ __align__(16) float sm[];
    float* as_  = sm;
    float* csm  = sm + AT_CSM;
    float* mxb  = sm + AT_MAX;
    const uint32_t us_base = smem_u32(sm + AT_US0);

    const int tid  = threadIdx.x;
    const int wid  = tid >> 5;
    const int lane = tid & 31;
    const int g    = lane >> 2;
    const int t    = lane & 3;

    const int b  = blockIdx.x >> 5;
    const int p0 = (blockIdx.x & 31) << 7;
    const int wm   = (wid & 3) * 32;
    const int wn_i = wid >> 2;
    const int wn   = wn_i * 40;

    // ---- stage full A: 256 ci x 128 px, tf32-rounded ----
    const float* imgb = img + (size_t)b * CDIM * HW + p0;
    for (int i = tid; i < CDIM * 128; i += 256) {
        int ci = i >> 7, px = i & 127;
        as_[ci * A_RS + px] = to_tf32(imgb[ci * HW + px]);
    }

    const float* Ubase = g_U + ((size_t)b * NHEADS * CDIM) * LDIM;

    // stage U(0): h=0, kb=0
    {
        for (int it = 0; it < 3; it++) {
            int idx = tid + it * 256;
            if (idx < 640) {
                int row = idx / 20, ch = idx % 20;
                cp_async16(us_base + (uint32_t)(row * U_RS * 4 + ch * 16),
                           (const char*)Ubase + (size_t)row * 320 + ch * 16);
            }
        }
        CP_COMMIT();
    }
    __syncthreads();   // A staged

    for (int h = 0; h < NHEADS; h++) {
        if (tid < LDIM) csm[tid] = g_c[(b * NHEADS + h) * LDIM + tid];

        float c[2][5][4];
        #pragma unroll
        for (int mt = 0; mt < 2; mt++)
            #pragma unroll
            for (int nt = 0; nt < 5; nt++)
                #pragma unroll
                for (int i = 0; i < 4; i++) c[mt][nt][i] = 0.f;

        for (int kb = 0; kb < 8; kb++) {
            const int s = h * 8 + kb;
            // prefetch U(s+1) into the other buffer
            if (s + 1 < 64) {
                const uint32_t dst = us_base + (uint32_t)(((s + 1) & 1) * 32 * U_RS * 4);
                const float* src = Ubase + ((size_t)((s + 1) >> 3) * CDIM + ((s + 1) & 7) * 32) * LDIM;
                for (int it = 0; it < 3; it++) {
                    int idx = tid + it * 256;
                    if (idx < 640) {
                        int row = idx / 20, ch = idx % 20;
                        cp_async16(dst + (uint32_t)(row * U_RS * 4 + ch * 16),
                                   (const char*)src + (size_t)row * 320 + ch * 16);
                    }
                }
                CP_COMMIT();
                CP_WAIT1();
            } else {
                CP_WAIT0();
            }
            __syncthreads();   // U(s) visible to all

            const float* us_ = sm + AT_US0 + (s & 1) * 32 * U_RS;
            #pragma unroll
            for (int kc = 0; kc < 4; kc++) {
                uint32_t a[2][4];
                #pragma unroll
                for (int mt = 0; mt < 2; mt++) {
                    const float* p = &as_[(kb * 32 + kc * 8 + t) * A_RS + wm + mt * 16 + g];
                    a[mt][0] = __float_as_uint(p[0]);
                    a[mt][1] = __float_as_uint(p[8]);
                    a[mt][2] = __float_as_uint(p[4 * A_RS]);
                    a[mt][3] = __float_as_uint(p[4 * A_RS + 8]);
                }
                const float* ur = &us_[(kc * 8 + t) * U_RS + wn + g];
                #pragma unroll
                for (int nt = 0; nt < 5; nt++) {
                    uint32_t b0 = __float_as_uint(ur[nt * 8]);
                    uint32_t b1 = __float_as_uint(ur[nt * 8 + 4 * U_RS]);
                    mma_tf32(c[0][nt], a[0][0], a[0][1], a[0][2], a[0][3], b0, b1);
                    mma_tf32(c[1][nt], a[1][0], a[1][1], a[1][2], a[1][3], b0, b1);
                }
            }
            __syncthreads();   // all done reading U(s) before it is overwritten
        }

        // epilogue: +c[n], max, sigmoid*scale
        #pragma unroll
        for (int mt = 0; mt < 2; mt++) {
            #pragma unroll
            for (int rr = 0; rr < 2; rr++) {
                float mx = -1e30f;
                #pragma unroll
                for (int nt = 0; nt < 5; nt++) {
                    int n0 = wn + nt * 8 + 2 * t;
                    mx = fmaxf(mx, fmaxf(c[mt][nt][rr * 2] + csm[n0],
                                         c[mt][nt][rr * 2 + 1] + csm[n0 + 1]));
                }
                mx = fmaxf(mx, __shfl_xor_sync(0xFFFFFFFF, mx, 1));
                mx = fmaxf(mx, __shfl_xor_sync(0xFFFFFFFF, mx, 2));
                if (t == 0)
                    mxb[wn_i * 128 + wm + mt * 16 + rr * 8 + g] = mx;
            }
        }
        __syncthreads();
        if (tid < 128) {
            float z = fmaxf(mxb[tid], mxb[128 + tid]);
            float a = (1.0f / (1.0f + expf(-z))) * scale[h];
            g_attn[((b * NHEADS + h) << 12) + p0 + tid] = a;
        }
        __syncthreads();   // mxb/csm free for next head
    }
}

// ================= K2: conv — cp.async double-buffered pipeline =================
#define RAW_RS  70
#define RAW_CS  280
#define W_RS    136
// smem layout (floats): RAW0[2240] RAW1[2240] WS0[9792] WS1[9792] B2S[128]
#define CV_RAW0 0
#define CV_RAW1 2240
#define CV_WS0  4480
#define CV_WS1  (4480 + 9792)
#define CV_B2S  (4480 + 2 * 9792)
#define CV_TOT  (CV_B2S + 128)

__global__ void __launch_bounds__(256) conv_mma_kernel(
    const float* __restrict__ img, float* __restrict__ out) {

    extern __shared__ __align__(16) float sm[];
    const uint32_t sbase = smem_u32(sm);
    float* b2s = sm + CV_B2S;

    const int tid  = threadIdx.x;
    const int wid  = tid >> 5;
    const int lane = tid & 31;
    const int g    = lane >> 2;
    const int t    = lane & 3;

    const int bM = blockIdx.x;
    const int bN = blockIdx.y;
    const int b  = bM >> 5;
    const int y0 = (bM & 31) << 1;
    const int wm = (wid & 3) * 32;
    const int wn = (wid >> 2) * 64;

    const float* imgb = img + (size_t)b * CDIM * HW;
    const float* wsrc0 = g_wB + (size_t)bN * 128;

    if (tid < 128) b2s[tid] = g_beta2[bN * 128 + tid];

    // ---- weight stage: 72 rows x 128 co, 16B chunks via cp.async ----
    auto stage_w = [&](int cib, int buf) {
        const uint32_t dst = sbase + (uint32_t)((buf ? CV_WS1 : CV_WS0) * 4);
        #pragma unroll
        for (int it = 0; it < 9; it++) {
            int idx = tid + it * 256;            // 2304 chunks
            int row = idx >> 5;                  // tap*8+ci
            int ch  = idx & 31;
            int tap = row >> 3, ci = row & 7;
            cp_async16(dst + (uint32_t)(row * W_RS * 4 + ch * 16),
                       wsrc0 + ((size_t)(tap * CDIM + cib * 8 + ci)) * CDIM + ch * 4);
        }
    };
    // ---- raw LDG into regs ----
    float v[9];
    auto ldg_raw = [&](int cib) {
        #pragma unroll
        for (int it = 0; it < 9; it++) {
            int i = tid + it * 256;
            float x = 0.f;
            if (i < 2112) {
                int ci = i / 264;
                int r  = i % 264;
                int ry = r / 66, rx = r % 66;
                int gy = y0 - 1 + ry;
                int gx = rx - 1;
                if ((unsigned)gy < 64u && (unsigned)gx < 64u)
                    x = imgb[(cib * 8 + ci) * HW + (gy << 6) + gx];
            }
            v[it] = x;
        }
    };
    auto sts_raw = [&](int buf) {
        float* dst = sm + (buf ? CV_RAW1 : CV_RAW0);
        #pragma unroll
        for (int it = 0; it < 9; it++) {
            int i = tid + it * 256;
            if (i < 2112) {
                int ci = i / 264;
                int r  = i % 264;
                int ry = r / 66, rx = r % 66;
                dst[ci * RAW_CS + ry * RAW_RS + rx] = to_tf32(v[it]);
            }
        }
    };

    float c[2][8][4];
    #pragma unroll
    for (int mt = 0; mt < 2; mt++)
        #pragma unroll
        for (int nt = 0; nt < 8; nt++)
            #pragma unroll
            for (int i = 0; i < 4; i++) c[mt][nt][i] = 0.f;

    // ---- prolog ----
    stage_w(0, 0); CP_COMMIT();
    ldg_raw(0); sts_raw(0);
    stage_w(1, 1); CP_COMMIT();
    CP_WAIT1();            // weights(0) done
    __syncthreads();       // raw(0) + weights(0) visible

    for (int cib = 0; cib < 32; cib++) {
        const int cur = cib & 1, nxt = cur ^ 1;
        if (cib + 1 < 32) ldg_raw(cib + 1);

        const float* raw = sm + (cur ? CV_RAW1 : CV_RAW0);
        const float* wsm = sm + (cur ? CV_WS1  : CV_WS0);

        for (int ky = 0; ky < 3; ky++) {
            #pragma unroll
            for (int kx = 0; kx < 3; kx++) {
                const int tap = ky * 3 + kx;
                uint32_t a[2][4];
                #pragma unroll
                for (int mt = 0; mt < 2; mt++) {
                    int m    = wm + mt * 16 + g;
                    int prow = m >> 6, pcol = m & 63;
                    const float* p = &raw[t * RAW_CS + (prow + ky) * RAW_RS + (pcol + kx)];
                    a[mt][0] = __float_as_uint(p[0]);
                    a[mt][1] = __float_as_uint(p[8]);
                    a[mt][2] = __float_as_uint(p[4 * RAW_CS]);
                    a[mt][3] = __float_as_uint(p[4 * RAW_CS + 8]);
                }
                const float* wrow = &wsm[(tap * 8 + t) * W_RS + wn + g];
                #pragma unroll
                for (int nt = 0; nt < 8; nt++) {
                    uint32_t b0 = __float_as_uint(wrow[nt * 8]);
                    uint32_t b1 = __float_as_uint(wrow[nt * 8 + 4 * W_RS]);
                    mma_tf32(c[0][nt], a[0][0], a[0][1], a[0][2], a[0][3], b0, b1);
                    mma_tf32(c[1][nt], a[1][0], a[1][1], a[1][2], a[1][3], b0, b1);
                }
            }
        }

        if (cib + 1 < 32) sts_raw(nxt);
        __syncthreads();                   // done reading cur bufs; raw(nxt) written
        if (cib + 2 < 32) {
            stage_w(cib + 2, cur); CP_COMMIT(); CP_WAIT1();
        } else if (cib + 1 < 32) {
            CP_WAIT0();
        }
        __syncthreads();                   // weights(cib+1) visible to all
    }

    // ---- epilogue ----
    #pragma unroll
    for (int mt = 0; mt < 2; mt++) {
        #pragma unroll
        for (int rr = 0; rr < 2; rr++) {
            int m   = wm + mt * 16 + g + rr * 8;
            int pix = (y0 << 6) + m;
            #pragma unroll
            for (int nt = 0; nt < 8; nt++) {
                int co = bN * 128 + wn + nt * 8 + 2 * t;
                float gate = g_attn[((b * NHEADS + (co >> 5)) << 12) + pix];
                float v0 = c[mt][nt][rr * 2 + 0] + b2s[wn + nt * 8 + 2 * t];
                float v1 = c[mt][nt][rr * 2 + 1] + b2s[wn + nt * 8 + 2 * t + 1];
                out[(((size_t)b * CDIM + co) << 12) + pix]     = v0 * gate;
                out[(((size_t)b * CDIM + co + 1) << 12) + pix] = v1 * gate;
            }
        }
    }
}

// ================= launch =================
extern "C" void kernel_launch(void* const* d_in, const int* in_sizes, int n_in,
                              void* d_out, int out_size) {
    const float* img_feat   = (const float*)d_in[0];
    const float* text_feats = (const float*)d_in[1];
    const float* proj_w     = (const float*)d_in[2];
    const float* proj_b     = (const float*)d_in[3];
    const float* attn_bias  = (const float*)d_in[4];
    const float* scale      = (const float*)d_in[5];
    const float* conv_w     = (const float*)d_in[6];
    const float* bn_gamma   = (const float*)d_in[7];
    const float* bn_beta    = (const float*)d_in[8];
    const float* bn_mean    = (const float*)d_in[9];
    const float* bn_var     = (const float*)d_in[10];
    float* out = (float*)d_out;

    static int attr_set = 0;
    if (!attr_set) {
        cudaFuncSetAttribute(attn_mma_kernel,
                             cudaFuncAttributeMaxDynamicSharedMemorySize, AT_TOT * 4);
        cudaFuncSetAttribute(conv_mma_kernel,
                             cudaFuncAttributeMaxDynamicSharedMemorySize, CV_TOT * 4);
        attr_set = 1;
    }

    prep_kernel<<<(CDIM * CDIM * 9 + 255) / 256, 256>>>(conv_w, bn_gamma, bn_beta, bn_mean, bn_var);

    dim3 gp(BDIM, NHEADS);
    prep_attn_kernel<<<gp, 256>>>(text_feats, proj_w, proj_b, attn_bias);

    attn_mma_kernel<<<BDIM * 32, 256, AT_TOT * 4>>>(img_feat, scale);

    dim3 g2(256, 2);
    conv_mma_kernel<<<g2, 256, CV_TOT * 4>>>(img_feat, out);
}

// round 7
// speedup vs baseline: 2.9688x; 1.0036x over previous
#include <cuda_runtime.h>
#include <cstdint>
#include <math.h>

#define NHEADS 8
#define HC     32
#define HW     4096
#define CDIM   256
#define BDIM   8
#define LDIM   80

// ================= scratch =================
__device__ float g_wB[9 * CDIM * CDIM];            // [tap][ci][co], BN-folded, tf32-rounded
__device__ float g_beta2[CDIM];
__device__ float g_attn[BDIM * NHEADS * HW];
__device__ float g_U[BDIM * NHEADS * CDIM * LDIM]; // [bh][ci][n], tf32-rounded, incl 1/sqrt(hc)
__device__ float g_c[BDIM * NHEADS * LDIM];

__device__ __forceinline__ float to_tf32(float x) {
    uint32_t u;
    asm("cvt.rna.tf32.f32 %0, %1;" : "=r"(u) : "f"(x));
    return __uint_as_float(u);
}
__device__ __forceinline__ uint32_t smem_u32(const void* p) {
    uint32_t a;
    asm("{ .reg .u64 t; cvta.to.shared.u64 t, %1; cvt.u32.u64 %0, t; }" : "=r"(a) : "l"(p));
    return a;
}
__device__ __forceinline__ void cp_async16(uint32_t dst, const void* src) {
    asm volatile("cp.async.ca.shared.global [%0], [%1], 16;" :: "r"(dst), "l"(src));
}
#define CP_COMMIT() asm volatile("cp.async.commit_group;" ::: "memory")
#define CP_WAIT2()  asm volatile("cp.async.wait_group 2;" ::: "memory")
#define CP_WAIT1()  asm volatile("cp.async.wait_group 1;" ::: "memory")
#define CP_WAIT0()  asm volatile("cp.async.wait_group 0;" ::: "memory")

__device__ __forceinline__ void mma_tf32(float* c,
                                         uint32_t a0, uint32_t a1, uint32_t a2, uint32_t a3,
                                         uint32_t b0, uint32_t b1) {
    asm volatile(
        "mma.sync.aligned.m16n8k8.row.col.f32.tf32.tf32.f32 "
        "{%0,%1,%2,%3}, {%4,%5,%6,%7}, {%8,%9}, {%0,%1,%2,%3};"
        : "+f"(c[0]), "+f"(c[1]), "+f"(c[2]), "+f"(c[3])
        : "r"(a0), "r"(a1), "r"(a2), "r"(a3), "r"(b0), "r"(b1));
}

// ================= K0: conv weight prep =================
__global__ void prep_kernel(const float* __restrict__ conv_w,
                            const float* __restrict__ gamma,
                            const float* __restrict__ beta,
                            const float* __restrict__ mean,
                            const float* __restrict__ var) {
    int idx = blockIdx.x * 256 + threadIdx.x;
    if (idx < CDIM * CDIM * 9) {
        int co  = idx / (CDIM * 9);
        int r   = idx % (CDIM * 9);
        int ci  = r / 9;
        int tap = r % 9;
        float inv = gamma[co] * rsqrtf(var[co] + 1e-3f);
        g_wB[(tap * CDIM + ci) * CDIM + co] = to_tf32(conv_w[idx] * inv);
    }
    if (idx < CDIM) {
        float inv = gamma[idx] * rsqrtf(var[idx] + 1e-3f);
        g_beta2[idx] = beta[idx] - mean[idx] * inv;
    }
}

// ================= K0b: attn prep — grid (B, H, 4 ci-chunks) =================
__global__ void __launch_bounds__(256) prep_attn_kernel(
    const float* __restrict__ text,
    const float* __restrict__ proj_w,
    const float* __restrict__ proj_b,
    const float* __restrict__ attn_bias) {

    __shared__ float W_s[HC * 64];      // [cc][ci_local]
    __shared__ float T_s[LDIM * 33];

    const int tid = threadIdx.x;
    const int b   = blockIdx.x;
    const int h   = blockIdx.y;
    const int ci0 = blockIdx.z * 64;
    const float invs = 0.17677669529663687f;

    for (int i = tid; i < HC * 64; i += 256) {
        int cc = i >> 6, cil = i & 63;
        W_s[i] = proj_w[(h * HC + cc) * CDIM + ci0 + cil];
    }
    for (int i = tid; i < LDIM * HC; i += 256) {
        int n = i >> 5, cc = i & 31;
        T_s[n * 33 + cc] = text[(b * LDIM + n) * CDIM + h * HC + cc];
    }
    __syncthreads();

    for (int i = tid; i < 64 * LDIM; i += 256) {
        int cil = i / LDIM, n = i % LDIM;
        float u = 0.f;
        #pragma unroll
        for (int cc = 0; cc < HC; cc++)
            u += W_s[cc * 64 + cil] * T_s[n * 33 + cc];
        g_U[((b * NHEADS + h) * CDIM + ci0 + cil) * LDIM + n] = to_tf32(u * invs);
    }
    if (blockIdx.z == 0 && tid < LDIM) {
        float cb = 0.f;
        #pragma unroll
        for (int cc = 0; cc < HC; cc++)
            cb += proj_b[h * HC + cc] * T_s[tid * 33 + cc];
        g_c[(b * NHEADS + h) * LDIM + tid] = cb * invs + attn_bias[h];
    }
}

// ================= K1: attn gate — A resident, 4-deep U ring, 1 barrier/iter =================
#define A_RS 136
#define U_RS 88
#define AT_US0  (256 * A_RS)
#define AT_CSM  (AT_US0 + 4 * 32 * U_RS)
#define AT_MAX  (AT_CSM + 80)
#define AT_TOT  (AT_MAX + 256)

__global__ void __launch_bounds__(256) attn_mma_kernel(
    const float* __restrict__ img, const float* __restrict__ scale) {

    extern __shared__ __align__(16) float sm[];
    float* as_ = sm;
    float* csm = sm + AT_CSM;
    float* mxb = sm + AT_MAX;
    const uint32_t us_base = smem_u32(sm + AT_US0);

    const int tid  = threadIdx.x;
    const int wid  = tid >> 5;
    const int lane = tid & 31;
    const int g    = lane >> 2;
    const int t    = lane & 3;

    const int b  = blockIdx.x >> 5;
    const int p0 = (blockIdx.x & 31) << 7;
    const int wm   = (wid & 3) * 32;
    const int wn_i = wid >> 2;
    const int wn   = wn_i * 40;

    const float* Ubase = g_U + ((size_t)b * NHEADS * CDIM) * LDIM;

    auto issue_U = [&](int s, int buf) {
        const uint32_t dst = us_base + (uint32_t)(buf * 32 * U_RS * 4);
        const float* src = Ubase + ((size_t)(s >> 3) * CDIM + (s & 7) * 32) * LDIM;
        #pragma unroll
        for (int it = 0; it < 3; it++) {
            int idx = tid + it * 256;
            if (idx < 640) {
                int row = idx / 20, ch = idx % 20;
                cp_async16(dst + (uint32_t)(row * U_RS * 4 + ch * 16),
                           (const char*)src + (size_t)row * 320 + ch * 16);
            }
        }
        CP_COMMIT();
    };

    // prolog: prefetch U(0..2)
    issue_U(0, 0);
    issue_U(1, 1);
    issue_U(2, 2);

    // stage full A: 256 ci x 128 px, tf32-rounded
    const float* imgb = img + (size_t)b * CDIM * HW + p0;
    for (int i = tid; i < CDIM * 128; i += 256) {
        int ci = i >> 7, px = i & 127;
        as_[ci * A_RS + px] = to_tf32(imgb[ci * HW + px]);
    }

    for (int h = 0; h < NHEADS; h++) {
        if (tid < LDIM) csm[tid] = g_c[(b * NHEADS + h) * LDIM + tid];

        float c[2][5][4];
        #pragma unroll
        for (int mt = 0; mt < 2; mt++)
            #pragma unroll
            for (int nt = 0; nt < 5; nt++)
                #pragma unroll
                for (int i = 0; i < 4; i++) c[mt][nt][i] = 0.f;

        for (int kb = 0; kb < 8; kb++) {
            const int s = h * 8 + kb;
            CP_WAIT2();          // group s complete
            __syncthreads();     // U(s) visible to all; all done with buf (s-1)&3
            if (s + 3 < 64) issue_U(s + 3, (s + 3) & 3);

            const float* us_ = sm + AT_US0 + (s & 3) * 32 * U_RS;
            #pragma unroll
            for (int kc = 0; kc < 4; kc++) {
                uint32_t a[2][4];
                #pragma unroll
                for (int mt = 0; mt < 2; mt++) {
                    const float* p = &as_[(kb * 32 + kc * 8 + t) * A_RS + wm + mt * 16 + g];
                    a[mt][0] = __float_as_uint(p[0]);
                    a[mt][1] = __float_as_uint(p[8]);
                    a[mt][2] = __float_as_uint(p[4 * A_RS]);
                    a[mt][3] = __float_as_uint(p[4 * A_RS + 8]);
                }
                const float* ur = &us_[(kc * 8 + t) * U_RS + wn + g];
                #pragma unroll
                for (int nt = 0; nt < 5; nt++) {
                    uint32_t b0 = __float_as_uint(ur[nt * 8]);
                    uint32_t b1 = __float_as_uint(ur[nt * 8 + 4 * U_RS]);
                    mma_tf32(c[0][nt], a[0][0], a[0][1], a[0][2], a[0][3], b0, b1);
                    mma_tf32(c[1][nt], a[1][0], a[1][1], a[1][2], a[1][3], b0, b1);
                }
            }
        }

        // epilogue: +c[n], max over tokens, sigmoid*scale
        #pragma unroll
        for (int mt = 0; mt < 2; mt++) {
            #pragma unroll
            for (int rr = 0; rr < 2; rr++) {
                float mx = -1e30f;
                #pragma unroll
                for (int nt = 0; nt < 5; nt++) {
                    int n0 = wn + nt * 8 + 2 * t;
                    mx = fmaxf(mx, fmaxf(c[mt][nt][rr * 2] + csm[n0],
                                         c[mt][nt][rr * 2 + 1] + csm[n0 + 1]));
                }
                mx = fmaxf(mx, __shfl_xor_sync(0xFFFFFFFF, mx, 1));
                mx = fmaxf(mx, __shfl_xor_sync(0xFFFFFFFF, mx, 2));
                if (t == 0)
                    mxb[wn_i * 128 + wm + mt * 16 + rr * 8 + g] = mx;
            }
        }
        __syncthreads();
        if (tid < 128) {
            float z = fmaxf(mxb[tid], mxb[128 + tid]);
            float a = (1.0f / (1.0f + expf(-z))) * scale[h];
            g_attn[((b * NHEADS + h) << 12) + p0 + tid] = a;
        }
        __syncthreads();
    }
}

// ================= K2: conv — weight cp.async pipeline, 2 CTAs/SM =================
#define RAW_RS  70
#define RAW_CS  280
#define W_RS    136
#define CV_RAW0 0
#define CV_RAW1 2240
#define CV_WS0  4480
#define CV_WS1  (4480 + 9792)
#define CV_B2S  (4480 + 2 * 9792)
#define CV_TOT  (CV_B2S + 128)

__global__ void __launch_bounds__(256, 2) conv_mma_kernel(
    const float* __restrict__ img, float* __restrict__ out) {

    extern __shared__ __align__(16) float sm[];
    const uint32_t sbase = smem_u32(sm);
    float* b2s = sm + CV_B2S;

    const int tid  = threadIdx.x;
    const int wid  = tid >> 5;
    const int lane = tid & 31;
    const int g    = lane >> 2;
    const int t    = lane & 3;

    const int bM = blockIdx.x;
    const int bN = blockIdx.y;
    const int b  = bM >> 5;
    const int y0 = (bM & 31) << 1;
    const int wm = (wid & 3) * 32;
    const int wn = (wid >> 2) * 64;

    const float* imgb  = img + (size_t)b * CDIM * HW;
    const float* wsrc0 = g_wB + (size_t)bN * 128;

    if (tid < 128) b2s[tid] = g_beta2[bN * 128 + tid];

    auto stage_w = [&](int cib, int buf) {
        const uint32_t dst = sbase + (uint32_t)((buf ? CV_WS1 : CV_WS0) * 4);
        #pragma unroll
        for (int it = 0; it < 9; it++) {
            int idx = tid + it * 256;
            int row = idx >> 5;
            int ch  = idx & 31;
            int tap = row >> 3, ci = row & 7;
            cp_async16(dst + (uint32_t)(row * W_RS * 4 + ch * 16),
                       wsrc0 + ((size_t)(tap * CDIM + cib * 8 + ci)) * CDIM + ch * 4);
        }
        CP_COMMIT();
    };
    auto stage_raw = [&](int cib, int buf) {
        float* dst = sm + (buf ? CV_RAW1 : CV_RAW0);
        for (int i = tid; i < 2112; i += 256) {
            int ci = i / 264;
            int r  = i % 264;
            int ry = r / 66, rx = r % 66;
            int gy = y0 - 1 + ry;
            int gx = rx - 1;
            float x = 0.f;
            if ((unsigned)gy < 64u && (unsigned)gx < 64u)
                x = imgb[(cib * 8 + ci) * HW + (gy << 6) + gx];
            dst[ci * RAW_CS + ry * RAW_RS + rx] = to_tf32(x);
        }
    };

    float c[2][8][4];
    #pragma unroll
    for (int mt = 0; mt < 2; mt++)
        #pragma unroll
        for (int nt = 0; nt < 8; nt++)
            #pragma unroll
            for (int i = 0; i < 4; i++) c[mt][nt][i] = 0.f;

    // prolog
    stage_w(0, 0);
    stage_w(1, 1);
    stage_raw(0, 0);
    CP_WAIT1();          // weights(0) done
    __syncthreads();

    for (int cib = 0; cib < 32; cib++) {
        const int cur = cib & 1, nxt = cur ^ 1;
        const float* raw = sm + (cur ? CV_RAW1 : CV_RAW0);
        const float* wsm = sm + (cur ? CV_WS1  : CV_WS0);

        for (int ky = 0; ky < 3; ky++) {
            #pragma unroll
            for (int kx = 0; kx < 3; kx++) {
                const int tap = ky * 3 + kx;
                uint32_t a[2][4];
                #pragma unroll
                for (int mt = 0; mt < 2; mt++) {
                    int m    = wm + mt * 16 + g;
                    int prow = m >> 6, pcol = m & 63;
                    const float* p = &raw[t * RAW_CS + (prow + ky) * RAW_RS + (pcol + kx)];
                    a[mt][0] = __float_as_uint(p[0]);
                    a[mt][1] = __float_as_uint(p[8]);
                    a[mt][2] = __float_as_uint(p[4 * RAW_CS]);
                    a[mt][3] = __float_as_uint(p[4 * RAW_CS + 8]);
                }
                const float* wrow = &wsm[(tap * 8 + t) * W_RS + wn + g];
                #pragma unroll
                for (int nt = 0; nt < 8; nt++) {
                    uint32_t b0 = __float_as_uint(wrow[nt * 8]);
                    uint32_t b1 = __float_as_uint(wrow[nt * 8 + 4 * W_RS]);
                    mma_tf32(c[0][nt], a[0][0], a[0][1], a[0][2], a[0][3], b0, b1);
                    mma_tf32(c[1][nt], a[1][0], a[1][1], a[1][2], a[1][3], b0, b1);
                }
            }
        }

        if (cib + 1 < 32) stage_raw(cib + 1, nxt);   // writes other buffer: no barrier needed
        __syncthreads();                              // all MMAs on cur done
        if (cib + 2 < 32) {
            stage_w(cib + 2, cur);
            CP_WAIT1();
        } else if (cib + 1 < 32) {
            CP_WAIT0();
        }
        __syncthreads();                              // weights(cib+1) visible
    }

    // epilogue
    #pragma unroll
    for (int mt = 0; mt < 2; mt++) {
        #pragma unroll
        for (int rr = 0; rr < 2; rr++) {
            int m   = wm + mt * 16 + g + rr * 8;
            int pix = (y0 << 6) + m;
            #pragma unroll
            for (int nt = 0; nt < 8; nt++) {
                int co = bN * 128 + wn + nt * 8 + 2 * t;
                float gate = g_attn[((b * NHEADS + (co >> 5)) << 12) + pix];
                float v0 = c[mt][nt][rr * 2 + 0] + b2s[wn + nt * 8 + 2 * t];
                float v1 = c[mt][nt][rr * 2 + 1] + b2s[wn + nt * 8 + 2 * t + 1];
                out[(((size_t)b * CDIM + co) << 12) + pix]     = v0 * gate;
                out[(((size_t)b * CDIM + co + 1) << 12) + pix] = v1 * gate;
            }
        }
    }
}

// ================= launch =================
extern "C" void kernel_launch(void* const* d_in, const int* in_sizes, int n_in,
                              void* d_out, int out_size) {
    const float* img_feat   = (const float*)d_in[0];
    const float* text_feats = (const float*)d_in[1];
    const float* proj_w     = (const float*)d_in[2];
    const float* proj_b     = (const float*)d_in[3];
    const float* attn_bias  = (const float*)d_in[4];
    const float* scale      = (const float*)d_in[5];
    const float* conv_w     = (const float*)d_in[6];
    const float* bn_gamma   = (const float*)d_in[7];
    const float* bn_beta    = (const float*)d_in[8];
    const float* bn_mean    = (const float*)d_in[9];
    const float* bn_var     = (const float*)d_in[10];
    float* out = (float*)d_out;

    static int attr_set = 0;
    if (!attr_set) {
        cudaFuncSetAttribute(attn_mma_kernel,
                             cudaFuncAttributeMaxDynamicSharedMemorySize, AT_TOT * 4);
        cudaFuncSetAttribute(conv_mma_kernel,
                             cudaFuncAttributeMaxDynamicSharedMemorySize, CV_TOT * 4);
        attr_set = 1;
    }

    prep_kernel<<<(CDIM * CDIM * 9 + 255) / 256, 256>>>(conv_w, bn_gamma, bn_beta, bn_mean, bn_var);

    dim3 gp(BDIM, NHEADS, 4);
    prep_attn_kernel<<<gp, 256>>>(text_feats, proj_w, proj_b, attn_bias);

    attn_mma_kernel<<<BDIM * 32, 256, AT_TOT * 4>>>(img_feat, scale);

    dim3 g2(256, 2);
    conv_mma_kernel<<<g2, 256, CV_TOT * 4>>>(img_feat, out);
}